// round 13
// baseline (speedup 1.0000x reference)
#include <cuda_runtime.h>
#include <cuda_bf16.h>
#include <cstdint>

// Problem constants
#define LAT    4
#define MM     1024
#define DIM    16
#define PP     16384
#define MTILE  64             // codes per CTA (4 warps x m16)
#define PTILE  128            // points per staged tile
#define PSPLIT 32
#define PCHUNK (PP / PSPLIT)  // 512
#define NITER  (PCHUNK / PTILE)  // 4
#define NT     128
#define NBLOCKS (LAT * (MM / MTILE) * PSPLIT)  // 4*16*32 = 2048
#define ZS     136            // padded row stride (words) -> conflict-free LDS

__device__ float    g_part[PSPLIT * LAT * MM];
__device__ unsigned g_ctr = 0;

__device__ __forceinline__ float ex2f(float x) {
    float y; asm("ex2.approx.ftz.f32 %0, %1;" : "=f"(y) : "f"(x)); return y;
}
// pack {low=a, high=b} as bf16x2
__device__ __forceinline__ uint32_t pk2(float a, float b) {
    uint32_t r; asm("cvt.rn.bf16x2.f32 %0, %1, %2;" : "=r"(r) : "f"(b), "f"(a)); return r;
}
__device__ __forceinline__ float bfhi(float v) {
    return __bfloat162float(__float2bfloat16(v));
}
// m16n8k16 row.col bf16 -> f32 accumulate (baseline PTX, fallback HMMA on sm_103)
__device__ __forceinline__ void mma_bf16(float& c0, float& c1, float& c2, float& c3,
                                         uint32_t a0, uint32_t a1, uint32_t a2, uint32_t a3,
                                         uint32_t b0, uint32_t b1) {
    asm volatile("mma.sync.aligned.m16n8k16.row.col.f32.bf16.bf16.f32 "
                 "{%0,%1,%2,%3}, {%4,%5,%6,%7}, {%8,%9}, {%0,%1,%2,%3};"
                 : "+f"(c0), "+f"(c1), "+f"(c2), "+f"(c3)
                 : "r"(a0), "r"(a1), "r"(a2), "r"(a3), "r"(b0), "r"(b1));
}

__global__ __launch_bounds__(NT)
void latent_hmma_kernel(const float* __restrict__ z,
                        const float* __restrict__ e,
                        const float* __restrict__ log_sigma,
                        float* __restrict__ out) {
    __shared__ uint32_t zh_pk[8 * ZS];   // {z[2k],z[2k+1]} hi, [k2][p] stride ZS
    __shared__ uint32_t zl_pk[8 * ZS];   // lo residual
    __shared__ float    azsq[PTILE];     // A*||z_p||^2
    __shared__ float    sred[NT];
    __shared__ unsigned is_last;

    const int b   = blockIdx.x;
    const int l   = b >> 9;          // 0..3   (512 blocks per latent)
    const int r   = b & 511;
    const int mt  = r >> 5;          // 0..15
    const int ps  = r & 31;          // 0..31
    const int m0  = mt * MTILE;
    const int tid = threadIdx.x;
    const int w   = tid >> 5;        // warp 0..3
    const int ln  = tid & 31;
    const int q   = ln & 3;          // k-quad
    const int cg  = ln >> 2;         // col group 0..7

    const float sig = log_sigma[0];
    const float A   = -0.5f * __expf(-2.0f * sig) * 1.4426950408889634f;
    const float kk  = -2.0f * A;     // positive

    // ---- build A fragments (e rows, hi/lo split) once; rows r0, r0+8 ----
    uint32_t ah0, ah1, ah2, ah3, al0, al1, al2, al3;
    float ae0, ae1;
    {
        const int rr0 = m0 + w * 16 + cg;
        const float* e0 = e + (size_t)(l * MM + rr0) * DIM;
        const float* e1 = e0 + 8 * DIM;
        float v0[DIM], v1[DIM];
        #pragma unroll
        for (int d4 = 0; d4 < 4; ++d4) {
            float4 f0 = *(const float4*)(e0 + d4 * 4);
            float4 f1 = *(const float4*)(e1 + d4 * 4);
            v0[d4*4+0] = f0.x; v0[d4*4+1] = f0.y; v0[d4*4+2] = f0.z; v0[d4*4+3] = f0.w;
            v1[d4*4+0] = f1.x; v1[d4*4+1] = f1.y; v1[d4*4+2] = f1.z; v1[d4*4+3] = f1.w;
        }
        float s0 = 0.f, s1 = 0.f;
        #pragma unroll
        for (int d = 0; d < DIM; ++d) { s0 = fmaf(v0[d], v0[d], s0); s1 = fmaf(v1[d], v1[d], s1); }
        ae0 = A * s0; ae1 = A * s1;

        const int c0 = 2 * q, c8 = 2 * q + 8;
        float h;
        h = bfhi(v0[c0]);   float h2 = bfhi(v0[c0+1]);
        ah0 = pk2(h, h2);   al0 = pk2(v0[c0]-h, v0[c0+1]-h2);
        h = bfhi(v1[c0]);   h2 = bfhi(v1[c0+1]);
        ah1 = pk2(h, h2);   al1 = pk2(v1[c0]-h, v1[c0+1]-h2);
        h = bfhi(v0[c8]);   h2 = bfhi(v0[c8+1]);
        ah2 = pk2(h, h2);   al2 = pk2(v0[c8]-h, v0[c8+1]-h2);
        h = bfhi(v1[c8]);   h2 = bfhi(v1[c8+1]);
        ah3 = pk2(h, h2);   al3 = pk2(v1[c8]-h, v1[c8+1]-h2);
    }

    const float* zbase = z + (size_t)((l * DIM) << 10);

    float ms0 = 0.f, ms1 = 0.f;

    for (int it = 0; it < NITER; ++it) {
        // ---- stage z tile: thread = one point ----
        {
            const int p  = ps * PCHUNK + it * PTILE + tid;
            const int n  = p >> 10;
            const int hw = p & 1023;
            const float* zp = zbase + ((size_t)(n * 64) << 10) + hw;
            float v[DIM];
            #pragma unroll
            for (int d = 0; d < DIM; ++d) v[d] = zp[(size_t)d << 10];
            float sq = 0.f;
            #pragma unroll
            for (int d = 0; d < DIM; ++d) sq = fmaf(v[d], v[d], sq);
            azsq[tid] = A * sq;
            #pragma unroll
            for (int k2 = 0; k2 < 8; ++k2) {
                const float h0 = bfhi(v[2*k2]), h1 = bfhi(v[2*k2+1]);
                zh_pk[k2 * ZS + tid] = pk2(h0, h1);
                zl_pk[k2 * ZS + tid] = pk2(v[2*k2] - h0, v[2*k2+1] - h1);
            }
        }
        __syncthreads();

        // ---- 16 n-chunks of 8 points; warp covers its 16 m-rows ----
        #pragma unroll 4
        for (int nc = 0; nc < PTILE / 8; ++nc) {
            const int p0 = nc * 8;
            const int pc = p0 + cg;
            const uint32_t bh0 = zh_pk[q * ZS + pc];
            const uint32_t bh1 = zh_pk[(q + 4) * ZS + pc];
            const uint32_t bl0 = zl_pk[q * ZS + pc];
            const uint32_t bl1 = zl_pk[(q + 4) * ZS + pc];

            float c0 = 0.f, c1 = 0.f, c2 = 0.f, c3 = 0.f;
            mma_bf16(c0, c1, c2, c3, ah0, ah1, ah2, ah3, bh0, bh1);
            mma_bf16(c0, c1, c2, c3, al0, al1, al2, al3, bh0, bh1);
            mma_bf16(c0, c1, c2, c3, ah0, ah1, ah2, ah3, bl0, bl1);

            const float2 az = *(const float2*)&azsq[p0 + 2 * q];
            ms0 += ex2f(fmaf(kk, c0, az.x)) + ex2f(fmaf(kk, c1, az.y));
            ms1 += ex2f(fmaf(kk, c2, az.x)) + ex2f(fmaf(kk, c3, az.y));
        }
        __syncthreads();   // protect smem before next staging
    }

    // ---- reduce over the 4 lanes sharing each row, fold exp2(A||e||^2) ----
    ms0 += __shfl_xor_sync(0xffffffffu, ms0, 1);
    ms0 += __shfl_xor_sync(0xffffffffu, ms0, 2);
    ms1 += __shfl_xor_sync(0xffffffffu, ms1, 1);
    ms1 += __shfl_xor_sync(0xffffffffu, ms1, 2);
    if (q == 0) {
        const int mrow = m0 + w * 16 + cg;
        float* gp = g_part + (ps * LAT + l) * MM;
        gp[mrow]     = ms0 * ex2f(ae0);
        gp[mrow + 8] = ms1 * ex2f(ae1);
    }

    // ---- last-block finalize ----
    __threadfence();
    if (tid == 0) is_last = (atomicAdd(&g_ctr, 1u) == NBLOCKS - 1u);
    __syncthreads();
    if (!is_last) return;

    float local = 0.f;
    for (int j = tid; j < LAT * MM; j += NT) {
        float s = 0.f;
        #pragma unroll
        for (int p = 0; p < PSPLIT; ++p) s += g_part[p * (LAT * MM) + j];
        local += __logf(s);
    }
    sred[tid] = local;
    __syncthreads();
    for (int st = NT / 2; st > 0; st >>= 1) {
        if (tid < st) sred[tid] += sred[tid + st];
        __syncthreads();
    }
    if (tid == 0) {
        g_ctr = 0;
        out[0] = -sred[0] / (float)(LAT * MM)
               + 32.0f * (2.0f * sig - 1.0f)
               + logf(16384.0f);
    }
}

extern "C" void kernel_launch(void* const* d_in, const int* in_sizes, int n_in,
                              void* d_out, int out_size) {
    const float* z  = (const float*)d_in[0];
    const float* e  = (const float*)d_in[1];
    const float* ls = (const float*)d_in[2];
    float* out = (float*)d_out;

    latent_hmma_kernel<<<NBLOCKS, NT>>>(z, e, ls, out);
}

// round 15
// speedup vs baseline: 1.1412x; 1.1412x over previous
#include <cuda_runtime.h>
#include <cuda_bf16.h>
#include <cstdint>

// Problem constants
#define LAT    4
#define MM     1024
#define DIM    16
#define PP     16384
#define MTILE  64             // codes per CTA (4 warps x m16)
#define PTILE  128            // points per staged tile
#define PSPLIT 16
#define PCHUNK (PP / PSPLIT)  // 1024
#define NITER  (PCHUNK / PTILE)  // 8
#define NT     128
#define NBLOCKS (LAT * (MM / MTILE) * PSPLIT)  // 4*16*16 = 1024
#define ZS     136            // padded row stride (words) -> conflict-free LDS

__device__ float    g_part[PSPLIT * LAT * MM];
__device__ unsigned g_ctr = 0;

__device__ __forceinline__ float ex2f(float x) {
    float y; asm("ex2.approx.ftz.f32 %0, %1;" : "=f"(y) : "f"(x)); return y;
}
// pack {low=a, high=b} as bf16x2
__device__ __forceinline__ uint32_t pk2(float a, float b) {
    uint32_t r; asm("cvt.rn.bf16x2.f32 %0, %1, %2;" : "=r"(r) : "f"(b), "f"(a)); return r;
}
__device__ __forceinline__ float bfhi(float v) {
    return __bfloat162float(__float2bfloat16(v));
}
// m16n8k16 row.col bf16 -> f32 accumulate (fallback HMMA on sm_103)
__device__ __forceinline__ void mma_bf16(float& c0, float& c1, float& c2, float& c3,
                                         uint32_t a0, uint32_t a1, uint32_t a2, uint32_t a3,
                                         uint32_t b0, uint32_t b1) {
    asm volatile("mma.sync.aligned.m16n8k16.row.col.f32.bf16.bf16.f32 "
                 "{%0,%1,%2,%3}, {%4,%5,%6,%7}, {%8,%9}, {%0,%1,%2,%3};"
                 : "+f"(c0), "+f"(c1), "+f"(c2), "+f"(c3)
                 : "r"(a0), "r"(a1), "r"(a2), "r"(a3), "r"(b0), "r"(b1));
}

__global__ __launch_bounds__(NT)
void latent_hmma_kernel(const float* __restrict__ z,
                        const float* __restrict__ e,
                        const float* __restrict__ log_sigma,
                        float* __restrict__ out) {
    __shared__ uint32_t zh_pk[2][8 * ZS];   // double-buffered hi pairs [k2][p]
    __shared__ uint32_t zl_pk[2][8 * ZS];   // lo residual
    __shared__ float    azsq[2][PTILE];     // A*||z_p||^2
    __shared__ float    sred[NT];
    __shared__ unsigned is_last;

    const int b   = blockIdx.x;
    const int l   = b >> 8;          // 0..3   (256 blocks per latent)
    const int r   = b & 255;
    const int mt  = r >> 4;          // 0..15
    const int ps  = r & 15;          // 0..15
    const int m0  = mt * MTILE;
    const int tid = threadIdx.x;
    const int w   = tid >> 5;        // warp 0..3
    const int ln  = tid & 31;
    const int q   = ln & 3;          // k-quad
    const int cg  = ln >> 2;         // col group 0..7

    const float sig = log_sigma[0];
    const float A   = -0.5f * __expf(-2.0f * sig) * 1.4426950408889634f;
    const float kk  = -2.0f * A;

    // ---- build A fragments (e rows, hi/lo split) once; rows r0, r0+8 ----
    uint32_t ah0, ah1, ah2, ah3, al0, al1, al2, al3;
    float ae0, ae1;
    {
        const int rr0 = m0 + w * 16 + cg;
        const float* e0 = e + (size_t)(l * MM + rr0) * DIM;
        const float* e1 = e0 + 8 * DIM;
        float v0[DIM], v1[DIM];
        #pragma unroll
        for (int d4 = 0; d4 < 4; ++d4) {
            float4 f0 = *(const float4*)(e0 + d4 * 4);
            float4 f1 = *(const float4*)(e1 + d4 * 4);
            v0[d4*4+0] = f0.x; v0[d4*4+1] = f0.y; v0[d4*4+2] = f0.z; v0[d4*4+3] = f0.w;
            v1[d4*4+0] = f1.x; v1[d4*4+1] = f1.y; v1[d4*4+2] = f1.z; v1[d4*4+3] = f1.w;
        }
        float s0 = 0.f, s1 = 0.f;
        #pragma unroll
        for (int d = 0; d < DIM; ++d) { s0 = fmaf(v0[d], v0[d], s0); s1 = fmaf(v1[d], v1[d], s1); }
        ae0 = A * s0; ae1 = A * s1;

        const int c0 = 2 * q, c8 = 2 * q + 8;
        float h, h2;
        h = bfhi(v0[c0]);   h2 = bfhi(v0[c0+1]);
        ah0 = pk2(h, h2);   al0 = pk2(v0[c0]-h, v0[c0+1]-h2);
        h = bfhi(v1[c0]);   h2 = bfhi(v1[c0+1]);
        ah1 = pk2(h, h2);   al1 = pk2(v1[c0]-h, v1[c0+1]-h2);
        h = bfhi(v0[c8]);   h2 = bfhi(v0[c8+1]);
        ah2 = pk2(h, h2);   al2 = pk2(v0[c8]-h, v0[c8+1]-h2);
        h = bfhi(v1[c8]);   h2 = bfhi(v1[c8+1]);
        ah3 = pk2(h, h2);   al3 = pk2(v1[c8]-h, v1[c8+1]-h2);
    }

    const float* zbase = z + (size_t)((l * DIM) << 10);

    // load tile `it` into registers (16 coalesced LDG)
    float v[DIM];
    {
        const int p  = ps * PCHUNK + 0 * PTILE + tid;
        const int n  = p >> 10;
        const int hw = p & 1023;
        const float* zp = zbase + ((size_t)(n * 64) << 10) + hw;
        #pragma unroll
        for (int d = 0; d < DIM; ++d) v[d] = zp[(size_t)d << 10];
    }
    // stage tile 0 into buffer 0
    {
        float sq = 0.f;
        #pragma unroll
        for (int d = 0; d < DIM; ++d) sq = fmaf(v[d], v[d], sq);
        azsq[0][tid] = A * sq;
        #pragma unroll
        for (int k2 = 0; k2 < 8; ++k2) {
            const float h0 = bfhi(v[2*k2]), h1 = bfhi(v[2*k2+1]);
            zh_pk[0][k2 * ZS + tid] = pk2(h0, h1);
            zl_pk[0][k2 * ZS + tid] = pk2(v[2*k2] - h0, v[2*k2+1] - h1);
        }
    }
    __syncthreads();

    float ms0 = 0.f, ms1 = 0.f;

    for (int it = 0; it < NITER; ++it) {
        const int cur = it & 1;
        const int nxt = cur ^ 1;

        // ---- issue prefetch LDGs for tile it+1 (overlaps compute below) ----
        if (it + 1 < NITER) {
            const int p  = ps * PCHUNK + (it + 1) * PTILE + tid;
            const int n  = p >> 10;
            const int hw = p & 1023;
            const float* zp = zbase + ((size_t)(n * 64) << 10) + hw;
            #pragma unroll
            for (int d = 0; d < DIM; ++d) v[d] = zp[(size_t)d << 10];
        }

        // ---- compute on buffer `cur`: 16 n-chunks of 8 points ----
        const uint32_t* zh = zh_pk[cur];
        const uint32_t* zl = zl_pk[cur];
        const float*    az = azsq[cur];
        #pragma unroll 4
        for (int nc = 0; nc < PTILE / 8; ++nc) {
            const int p0 = nc * 8;
            const int pc = p0 + cg;
            const uint32_t bh0 = zh[q * ZS + pc];
            const uint32_t bh1 = zh[(q + 4) * ZS + pc];
            const uint32_t bl0 = zl[q * ZS + pc];
            const uint32_t bl1 = zl[(q + 4) * ZS + pc];

            float c0 = 0.f, c1 = 0.f, c2 = 0.f, c3 = 0.f;
            mma_bf16(c0, c1, c2, c3, ah0, ah1, ah2, ah3, bh0, bh1);
            mma_bf16(c0, c1, c2, c3, al0, al1, al2, al3, bh0, bh1);
            mma_bf16(c0, c1, c2, c3, ah0, ah1, ah2, ah3, bl0, bl1);

            const float2 a2 = *(const float2*)&az[p0 + 2 * q];
            ms0 += ex2f(fmaf(kk, c0, a2.x)) + ex2f(fmaf(kk, c1, a2.y));
            ms1 += ex2f(fmaf(kk, c2, a2.x)) + ex2f(fmaf(kk, c3, a2.y));
        }

        // ---- stage tile it+1 into buffer `nxt` ----
        if (it + 1 < NITER) {
            float sq = 0.f;
            #pragma unroll
            for (int d = 0; d < DIM; ++d) sq = fmaf(v[d], v[d], sq);
            azsq[nxt][tid] = A * sq;
            #pragma unroll
            for (int k2 = 0; k2 < 8; ++k2) {
                const float h0 = bfhi(v[2*k2]), h1 = bfhi(v[2*k2+1]);
                zh_pk[nxt][k2 * ZS + tid] = pk2(h0, h1);
                zl_pk[nxt][k2 * ZS + tid] = pk2(v[2*k2] - h0, v[2*k2+1] - h1);
            }
            __syncthreads();   // staging of `nxt` done before next iter reads it
        }
    }

    // ---- reduce over the 4 lanes sharing each row, fold exp2(A||e||^2) ----
    ms0 += __shfl_xor_sync(0xffffffffu, ms0, 1);
    ms0 += __shfl_xor_sync(0xffffffffu, ms0, 2);
    ms1 += __shfl_xor_sync(0xffffffffu, ms1, 1);
    ms1 += __shfl_xor_sync(0xffffffffu, ms1, 2);
    if (q == 0) {
        const int mrow = m0 + w * 16 + cg;
        float* gp = g_part + (ps * LAT + l) * MM;
        gp[mrow]     = ms0 * ex2f(ae0);
        gp[mrow + 8] = ms1 * ex2f(ae1);
    }

    // ---- last-block finalize ----
    __threadfence();
    if (tid == 0) is_last = (atomicAdd(&g_ctr, 1u) == NBLOCKS - 1u);
    __syncthreads();
    if (!is_last) return;

    float local = 0.f;
    for (int j = tid; j < LAT * MM; j += NT) {
        float s = 0.f;
        #pragma unroll
        for (int p = 0; p < PSPLIT; ++p) s += g_part[p * (LAT * MM) + j];
        local += __logf(s);
    }
    sred[tid] = local;
    __syncthreads();
    for (int st = NT / 2; st > 0; st >>= 1) {
        if (tid < st) sred[tid] += sred[tid + st];
        __syncthreads();
    }
    if (tid == 0) {
        g_ctr = 0;
        out[0] = -sred[0] / (float)(LAT * MM)
               + 32.0f * (2.0f * sig - 1.0f)
               + logf(16384.0f);
    }
}

extern "C" void kernel_launch(void* const* d_in, const int* in_sizes, int n_in,
                              void* d_out, int out_size) {
    const float* z  = (const float*)d_in[0];
    const float* e  = (const float*)d_in[1];
    const float* ls = (const float*)d_in[2];
    float* out = (float*)d_out;

    latent_hmma_kernel<<<NBLOCKS, NT>>>(z, e, ls, out);
}

// round 16
// speedup vs baseline: 1.3360x; 1.1707x over previous
#include <cuda_runtime.h>
#include <cuda_bf16.h>
#include <cstdint>

// Problem constants
#define LAT    4
#define MM     1024
#define DIM    16
#define PP     16384
#define MTILE  64             // codes per CTA (4 warps x m16)
#define PTILE  128            // points per staged tile
#define PSPLIT 16
#define PCHUNK (PP / PSPLIT)  // 1024
#define NITER  (PCHUNK / PTILE)  // 8
#define NT     128
#define NBLOCKS (LAT * (MM / MTILE) * PSPLIT)  // 1024
#define ZS     136            // padded row stride (words) -> conflict-free LDS

__device__ float    g_part[PSPLIT * LAT * MM];
__device__ unsigned g_ctr = 0;

__device__ __forceinline__ float ex2f(float x) {
    float y; asm("ex2.approx.ftz.f32 %0, %1;" : "=f"(y) : "f"(x)); return y;
}
// pack {low=a, high=b} as bf16x2
__device__ __forceinline__ uint32_t pk2(float a, float b) {
    uint32_t r; asm("cvt.rn.bf16x2.f32 %0, %1, %2;" : "=r"(r) : "f"(b), "f"(a)); return r;
}
__device__ __forceinline__ float bfhi(float v) {
    return __bfloat162float(__float2bfloat16(v));
}
// m16n8k16 row.col bf16 -> f32 accumulate (fallback HMMA on sm_103)
__device__ __forceinline__ void mma_bf16(float& c0, float& c1, float& c2, float& c3,
                                         uint32_t a0, uint32_t a1, uint32_t a2, uint32_t a3,
                                         uint32_t b0, uint32_t b1) {
    asm volatile("mma.sync.aligned.m16n8k16.row.col.f32.bf16.bf16.f32 "
                 "{%0,%1,%2,%3}, {%4,%5,%6,%7}, {%8,%9}, {%0,%1,%2,%3};"
                 : "+f"(c0), "+f"(c1), "+f"(c2), "+f"(c3)
                 : "r"(a0), "r"(a1), "r"(a2), "r"(a3), "r"(b0), "r"(b1));
}

__global__ __launch_bounds__(NT)
void latent_hmma_kernel(const float* __restrict__ z,
                        const float* __restrict__ e,
                        const float* __restrict__ log_sigma,
                        float* __restrict__ out) {
    __shared__ uint32_t zh_pk[2][8 * ZS];   // double-buffered bf16 pairs [k2][p]
    __shared__ float    azsq[2][PTILE];     // A*||z_p||^2
    __shared__ float    sred[NT];
    __shared__ unsigned is_last;

    const int b   = blockIdx.x;
    const int l   = b >> 8;          // 0..3   (256 blocks per latent)
    const int r   = b & 255;
    const int mt  = r >> 4;          // 0..15
    const int ps  = r & 15;          // 0..15
    const int m0  = mt * MTILE;
    const int tid = threadIdx.x;
    const int w   = tid >> 5;        // warp 0..3
    const int ln  = tid & 31;
    const int q   = ln & 3;          // k-quad
    const int cg  = ln >> 2;         // col group 0..7

    const float sig = log_sigma[0];
    const float A   = -0.5f * __expf(-2.0f * sig) * 1.4426950408889634f;
    const float kk  = -2.0f * A;     // positive

    // ---- build A fragments from e' = kk*e (hi/lo split of the SCALED rows) ----
    // MMA then produces kk*(e . zh) directly; epilogue needs no FFMA by kk.
    uint32_t ah0, ah1, ah2, ah3, al0, al1, al2, al3;
    float ae0, ae1;
    {
        const int rr0 = m0 + w * 16 + cg;
        const float* e0 = e + (size_t)(l * MM + rr0) * DIM;
        const float* e1 = e0 + 8 * DIM;
        float v0[DIM], v1[DIM];
        #pragma unroll
        for (int d4 = 0; d4 < 4; ++d4) {
            float4 f0 = *(const float4*)(e0 + d4 * 4);
            float4 f1 = *(const float4*)(e1 + d4 * 4);
            v0[d4*4+0] = f0.x; v0[d4*4+1] = f0.y; v0[d4*4+2] = f0.z; v0[d4*4+3] = f0.w;
            v1[d4*4+0] = f1.x; v1[d4*4+1] = f1.y; v1[d4*4+2] = f1.z; v1[d4*4+3] = f1.w;
        }
        float s0 = 0.f, s1 = 0.f;
        #pragma unroll
        for (int d = 0; d < DIM; ++d) { s0 = fmaf(v0[d], v0[d], s0); s1 = fmaf(v1[d], v1[d], s1); }
        ae0 = A * s0; ae1 = A * s1;

        // scale by kk, then split
        #pragma unroll
        for (int d = 0; d < DIM; ++d) { v0[d] *= kk; v1[d] *= kk; }

        const int c0 = 2 * q, c8 = 2 * q + 8;
        float h, h2;
        h = bfhi(v0[c0]);   h2 = bfhi(v0[c0+1]);
        ah0 = pk2(h, h2);   al0 = pk2(v0[c0]-h, v0[c0+1]-h2);
        h = bfhi(v1[c0]);   h2 = bfhi(v1[c0+1]);
        ah1 = pk2(h, h2);   al1 = pk2(v1[c0]-h, v1[c0+1]-h2);
        h = bfhi(v0[c8]);   h2 = bfhi(v0[c8+1]);
        ah2 = pk2(h, h2);   al2 = pk2(v0[c8]-h, v0[c8+1]-h2);
        h = bfhi(v1[c8]);   h2 = bfhi(v1[c8+1]);
        ah3 = pk2(h, h2);   al3 = pk2(v1[c8]-h, v1[c8+1]-h2);
    }

    const float* zbase = z + (size_t)((l * DIM) << 10);

    // prefetch tile 0 into registers (16 coalesced LDG)
    float v[DIM];
    {
        const int p  = ps * PCHUNK + tid;
        const int n  = p >> 10;
        const int hw = p & 1023;
        const float* zp = zbase + ((size_t)(n * 64) << 10) + hw;
        #pragma unroll
        for (int d = 0; d < DIM; ++d) v[d] = zp[(size_t)d << 10];
    }
    // stage tile 0 into buffer 0 (bf16 only; z^2 stays fp32)
    {
        float sq = 0.f;
        #pragma unroll
        for (int d = 0; d < DIM; ++d) sq = fmaf(v[d], v[d], sq);
        azsq[0][tid] = A * sq;
        #pragma unroll
        for (int k2 = 0; k2 < 8; ++k2)
            zh_pk[0][k2 * ZS + tid] = pk2(bfhi(v[2*k2]), bfhi(v[2*k2+1]));
    }
    __syncthreads();

    float ms0 = 0.f, ms1 = 0.f;

    for (int it = 0; it < NITER; ++it) {
        const int cur = it & 1;
        const int nxt = cur ^ 1;

        // prefetch LDGs for tile it+1 (overlap compute)
        if (it + 1 < NITER) {
            const int p  = ps * PCHUNK + (it + 1) * PTILE + tid;
            const int n  = p >> 10;
            const int hw = p & 1023;
            const float* zp = zbase + ((size_t)(n * 64) << 10) + hw;
            #pragma unroll
            for (int d = 0; d < DIM; ++d) v[d] = zp[(size_t)d << 10];
        }

        // compute on buffer cur: 16 n-chunks of 8 points
        const uint32_t* zh = zh_pk[cur];
        const float*    az = azsq[cur];
        #pragma unroll 4
        for (int nc = 0; nc < PTILE / 8; ++nc) {
            const int p0 = nc * 8;
            const int pc = p0 + cg;
            const uint32_t bh0 = zh[q * ZS + pc];
            const uint32_t bh1 = zh[(q + 4) * ZS + pc];

            // accumulator pre-loaded with A*||z||^2; MMA adds kk*(e.zh)
            const float2 a2 = *(const float2*)&az[p0 + 2 * q];
            float c0 = a2.x, c1 = a2.y, c2 = a2.x, c3 = a2.y;
            mma_bf16(c0, c1, c2, c3, ah0, ah1, ah2, ah3, bh0, bh1);
            mma_bf16(c0, c1, c2, c3, al0, al1, al2, al3, bh0, bh1);

            ms0 += ex2f(c0) + ex2f(c1);
            ms1 += ex2f(c2) + ex2f(c3);
        }

        // stage tile it+1 into buffer nxt
        if (it + 1 < NITER) {
            float sq = 0.f;
            #pragma unroll
            for (int d = 0; d < DIM; ++d) sq = fmaf(v[d], v[d], sq);
            azsq[nxt][tid] = A * sq;
            #pragma unroll
            for (int k2 = 0; k2 < 8; ++k2)
                zh_pk[nxt][k2 * ZS + tid] = pk2(bfhi(v[2*k2]), bfhi(v[2*k2+1]));
            __syncthreads();
        }
    }

    // ---- reduce over the 4 lanes sharing each row, fold exp2(A||e||^2) ----
    ms0 += __shfl_xor_sync(0xffffffffu, ms0, 1);
    ms0 += __shfl_xor_sync(0xffffffffu, ms0, 2);
    ms1 += __shfl_xor_sync(0xffffffffu, ms1, 1);
    ms1 += __shfl_xor_sync(0xffffffffu, ms1, 2);
    if (q == 0) {
        const int mrow = m0 + w * 16 + cg;
        float* gp = g_part + (ps * LAT + l) * MM;
        gp[mrow]     = ms0 * ex2f(ae0);
        gp[mrow + 8] = ms1 * ex2f(ae1);
    }

    // ---- last-block finalize ----
    __threadfence();
    if (tid == 0) is_last = (atomicAdd(&g_ctr, 1u) == NBLOCKS - 1u);
    __syncthreads();
    if (!is_last) return;

    float local = 0.f;
    for (int j = tid; j < LAT * MM; j += NT) {
        float s = 0.f;
        #pragma unroll
        for (int p = 0; p < PSPLIT; ++p) s += g_part[p * (LAT * MM) + j];
        local += __logf(s);
    }
    sred[tid] = local;
    __syncthreads();
    for (int st = NT / 2; st > 0; st >>= 1) {
        if (tid < st) sred[tid] += sred[tid + st];
        __syncthreads();
    }
    if (tid == 0) {
        g_ctr = 0;
        out[0] = -sred[0] / (float)(LAT * MM)
               + 32.0f * (2.0f * sig - 1.0f)
               + logf(16384.0f);
    }
}

extern "C" void kernel_launch(void* const* d_in, const int* in_sizes, int n_in,
                              void* d_out, int out_size) {
    const float* z  = (const float*)d_in[0];
    const float* e  = (const float*)d_in[1];
    const float* ls = (const float*)d_in[2];
    float* out = (float*)d_out;

    latent_hmma_kernel<<<NBLOCKS, NT>>>(z, e, ls, out);
}